// round 6
// baseline (speedup 1.0000x reference)
#include <cuda_runtime.h>

// ---- constant-memory weights (populated per launch via captured D2D memcpys) ----
__constant__ float cWq[144];
__constant__ float cbq[12];
__constant__ float cWk[144];
__constant__ float cbk[12];
__constant__ float cWv[144];
__constant__ float cbv[12];
__constant__ float cWo[144];
__constant__ float cbo[12];
__constant__ float cW1[288];
__constant__ float cb1[24];
__constant__ float cW2[288];
__constant__ float cb2[12];

namespace {

constexpr int N = 8;      // seq len
constexpr int D = 12;     // embed dim
constexpr int F = 24;     // ff dim
constexpr int V = 128;    // vocab
constexpr int WARPS = 8;  // warps per block
constexpr int IPW = 4;    // items per warp (8 lanes each)
constexpr int THREADS = WARPS * 32;
constexpr int ITEMS_PER_BLOCK = WARPS * IPW;   // 32

#define F4C(p) (*reinterpret_cast<const float4*>(p))
#define F4(p)  (*reinterpret_cast<float4*>(p))

using ull = unsigned long long;

__device__ __forceinline__ ull pack2(float x, float y) {
    ull p; asm("mov.b64 %0, {%1, %2};" : "=l"(p) : "f"(x), "f"(y)); return p;
}
__device__ __forceinline__ void unpack2(ull p, float& x, float& y) {
    asm("mov.b64 {%0, %1}, %2;" : "=f"(x), "=f"(y) : "l"(p));
}
__device__ __forceinline__ void ffma2(ull& d, ull a, ull b) {
    asm("fma.rn.f32x2 %0, %1, %2, %0;" : "+l"(d) : "l"(a), "l"(b));
}

__global__ __launch_bounds__(THREADS, 3)
void tiny_transformer_kernel(
    const int*   __restrict__ x,
    const float* __restrict__ embed,
    const float* __restrict__ pos,
    const float* __restrict__ blm,
    float* __restrict__ out)
{
    // ---- shared: only lane-divergent data ----
    __shared__ __align__(16) float sEmb[V * D];    // natural [v][d] for gather
    __shared__ __align__(16) float sEmbT[D * V];   // transposed [d][v] for logits
    __shared__ __align__(16) float sPos[N * D];
    __shared__ __align__(16) float sBlm[V];
    __shared__ __align__(16) float sXf[WARPS][IPW * N * D];

    const int tid = threadIdx.x;

    for (int i = tid; i < V * D; i += THREADS) sEmb[i] = embed[i];
    for (int i = tid; i < D * V; i += THREADS) {
        int d = i >> 7, v = i & 127;
        sEmbT[i] = embed[v * D + d];
    }
    for (int i = tid; i < N * D; i += THREADS) sPos[i] = pos[i];
    for (int i = tid; i < V; i += THREADS) sBlm[i] = blm[i];
    __syncthreads();

    const int w    = tid >> 5;
    const int lane = tid & 31;
    const int n    = lane & 7;            // token index within item
    const int item_base = blockIdx.x * ITEMS_PER_BLOCK + w * IPW;

    // ---- phase 1: X = embed[x] + pos (smem gather, L1-free) ----
    const int tok = __ldg(&x[item_base * N + lane]);
    float X[D];
    #pragma unroll
    for (int c = 0; c < 3; c++) {
        float4 e = F4C(&sEmb[tok * D + 4 * c]);
        float4 p = F4C(&sPos[n * D + 4 * c]);
        X[4*c+0] = e.x + p.x; X[4*c+1] = e.y + p.y;
        X[4*c+2] = e.z + p.z; X[4*c+3] = e.w + p.w;
    }

    // ---- phase 2: Q,K,V per token (constant weights, uniform port) ----
    float Qr[D], Kr[D], Vr[D];
    #pragma unroll
    for (int d = 0; d < D; d++) {
        float q = cbq[d], k = cbk[d], v = cbv[d];
        #pragma unroll
        for (int e = 0; e < D; e++) {
            q += X[e] * cWq[d * D + e];
            k += X[e] * cWk[d * D + e];
            v += X[e] * cWv[d * D + e];
        }
        Qr[d] = q; Kr[d] = k; Vr[d] = v;
    }

    // ---- phase 3: scores via width-8 shuffles ----
    float S[N];
    {
        const float inv_scale = 0.28867513459481287f;  // 1/sqrt(12)
        #pragma unroll
        for (int m = 0; m < N; m++) {
            float acc = 0.f;
            #pragma unroll
            for (int e = 0; e < D; e++)
                acc += Qr[e] * __shfl_sync(0xffffffffu, Kr[e], m, 8);
            S[m] = (m <= n) ? acc * inv_scale : -1e30f;
        }
    }

    // ---- phase 4: softmax ----
    {
        float mx = S[0];
        #pragma unroll
        for (int m = 1; m < N; m++) mx = fmaxf(mx, S[m]);
        float sum = 0.f;
        #pragma unroll
        for (int m = 0; m < N; m++) { S[m] = __expf(S[m] - mx); sum += S[m]; }
        const float inv = 1.f / sum;
        #pragma unroll
        for (int m = 0; m < N; m++) S[m] *= inv;
    }

    // ---- phase 5: A = softmax @ V via shuffles ----
    float A[D];
    #pragma unroll
    for (int e = 0; e < D; e++) A[e] = 0.f;
    #pragma unroll
    for (int m = 0; m < N; m++) {
        const float s = S[m];
        #pragma unroll
        for (int e = 0; e < D; e++)
            A[e] += s * __shfl_sync(0xffffffffu, Vr[e], m, 8);
    }

    // ---- phase 6: X += A @ Wo^T + bo (constant weights) ----
    #pragma unroll
    for (int d = 0; d < D; d++) {
        float acc = cbo[d];
        #pragma unroll
        for (int e = 0; e < D; e++) acc += A[e] * cWo[d * D + e];
        X[d] += acc;
    }

    // ---- phase 7: H = relu(X @ W1^T + b1) (constant weights) ----
    float H[F];
    #pragma unroll
    for (int f = 0; f < F; f++) {
        float acc = cb1[f];
        #pragma unroll
        for (int e = 0; e < D; e++) acc += X[e] * cW1[f * D + e];
        H[f] = fmaxf(acc, 0.f);
    }

    // ---- phase 8: X += H @ W2^T + b2 (constant weights) ----
    #pragma unroll
    for (int d = 0; d < D; d++) {
        float acc = cb2[d];
        #pragma unroll
        for (int f = 0; f < F; f++) acc += H[f] * cW2[d * F + f];
        X[d] += acc;
    }

    // ---- hand off final X to warp-wide logits phase ----
    {
        float* dst = &sXf[w][lane * D];
        F4(dst)     = make_float4(X[0], X[1], X[2],  X[3]);
        F4(dst + 4) = make_float4(X[4], X[5], X[6],  X[7]);
        F4(dst + 8) = make_float4(X[8], X[9], X[10], X[11]);
    }
    __syncwarp();

    // ---- phase 9: logits = Xf @ embed^T + b_lm (warp-wide, 32 rows, FFMA2) ----
    {
        const int v0 = lane * 4;
        ull e01[D], e23[D];
        #pragma unroll
        for (int d = 0; d < D; d++) {
            float4 e = F4C(&sEmbT[d * V + v0]);
            e01[d] = pack2(e.x, e.y);
            e23[d] = pack2(e.z, e.w);
        }
        const float4 bl = F4C(&sBlm[v0]);
        const ull bl01 = pack2(bl.x, bl.y);
        const ull bl23 = pack2(bl.z, bl.w);

        float* obase = out + (size_t)item_base * (N * V) + v0;
        const float* xf = sXf[w];

        for (int r = 0; r < IPW * N; r++) {
            float4 xa = F4C(&xf[r * D]);       // broadcast reads
            float4 xb = F4C(&xf[r * D + 4]);
            float4 xc = F4C(&xf[r * D + 8]);
            const float xr[D] = {xa.x, xa.y, xa.z, xa.w,
                                 xb.x, xb.y, xb.z, xb.w,
                                 xc.x, xc.y, xc.z, xc.w};
            ull a01 = bl01, a23 = bl23;
            #pragma unroll
            for (int d = 0; d < D; d++) {
                const ull xv2 = pack2(xr[d], xr[d]);
                ffma2(a01, xv2, e01[d]);
                ffma2(a23, xv2, e23[d]);
            }
            float4 acc;
            unpack2(a01, acc.x, acc.y);
            unpack2(a23, acc.z, acc.w);
            F4(&obase[(size_t)r * V]) = acc;   // coalesced 512B per warp-row
        }
    }
}

}  // namespace

extern "C" void kernel_launch(void* const* d_in, const int* in_sizes, int n_in,
                              void* d_out, int out_size)
{
    const int*   x     = (const int*)  d_in[0];
    const float* embed = (const float*)d_in[1];
    const float* pos   = (const float*)d_in[2];
    const float* blm   = (const float*)d_in[15];
    float* out = (float*)d_out;

    // stage weights into constant memory (graph-capturable D2D copies)
    void* p;
    cudaGetSymbolAddress(&p, cWq); cudaMemcpyAsync(p, d_in[3],  144 * 4, cudaMemcpyDeviceToDevice);
    cudaGetSymbolAddress(&p, cbq); cudaMemcpyAsync(p, d_in[4],   12 * 4, cudaMemcpyDeviceToDevice);
    cudaGetSymbolAddress(&p, cWk); cudaMemcpyAsync(p, d_in[5],  144 * 4, cudaMemcpyDeviceToDevice);
    cudaGetSymbolAddress(&p, cbk); cudaMemcpyAsync(p, d_in[6],   12 * 4, cudaMemcpyDeviceToDevice);
    cudaGetSymbolAddress(&p, cWv); cudaMemcpyAsync(p, d_in[7],  144 * 4, cudaMemcpyDeviceToDevice);
    cudaGetSymbolAddress(&p, cbv); cudaMemcpyAsync(p, d_in[8],   12 * 4, cudaMemcpyDeviceToDevice);
    cudaGetSymbolAddress(&p, cWo); cudaMemcpyAsync(p, d_in[9],  144 * 4, cudaMemcpyDeviceToDevice);
    cudaGetSymbolAddress(&p, cbo); cudaMemcpyAsync(p, d_in[10],  12 * 4, cudaMemcpyDeviceToDevice);
    cudaGetSymbolAddress(&p, cW1); cudaMemcpyAsync(p, d_in[11], 288 * 4, cudaMemcpyDeviceToDevice);
    cudaGetSymbolAddress(&p, cb1); cudaMemcpyAsync(p, d_in[12],  24 * 4, cudaMemcpyDeviceToDevice);
    cudaGetSymbolAddress(&p, cW2); cudaMemcpyAsync(p, d_in[13], 288 * 4, cudaMemcpyDeviceToDevice);
    cudaGetSymbolAddress(&p, cb2); cudaMemcpyAsync(p, d_in[14],  12 * 4, cudaMemcpyDeviceToDevice);

    const int batch  = in_sizes[0] / N;              // 32768
    const int blocks = batch / ITEMS_PER_BLOCK;      // 1024

    tiny_transformer_kernel<<<blocks, THREADS>>>(x, embed, pos, blm, out);
}

// round 7
// speedup vs baseline: 1.3975x; 1.3975x over previous
#include <cuda_runtime.h>

using ull = unsigned long long;

// ---- all weights in one constant struct (single memcpy node) ----
struct ConstW {
    ull pWq[72];   // [e][p] = (Wq[2p][e], Wq[2p+1][e])
    ull pWk[72];
    ull pWv[72];
    ull pWo[72];
    ull pW1[144];  // [e][p] p<12
    ull pW2[144];  // [f][p] p<6
    ull pbq[6], pbk[6], pbv[6], pbo[6], pb2[6], pb1[12];
};

__constant__ ConstW cw;
__device__ ConstW gStage;

namespace {

constexpr int N = 8;
constexpr int D = 12;
constexpr int F = 24;
constexpr int V = 128;
constexpr int WARPS = 8;
constexpr int IPW = 4;
constexpr int THREADS = WARPS * 32;
constexpr int ITEMS_PER_BLOCK = WARPS * IPW;   // 32

#define F4C(p) (*reinterpret_cast<const float4*>(p))
#define F4(p)  (*reinterpret_cast<float4*>(p))

__device__ __forceinline__ ull pack2(float x, float y) {
    ull p; asm("mov.b64 %0, {%1, %2};" : "=l"(p) : "f"(x), "f"(y)); return p;
}
__device__ __forceinline__ void unpack2(ull p, float& x, float& y) {
    asm("mov.b64 {%0, %1}, %2;" : "=f"(x), "=f"(y) : "l"(p));
}
__device__ __forceinline__ void ffma2(ull& d, ull a, ull b) {
    asm("fma.rn.f32x2 %0, %1, %2, %0;" : "+l"(d) : "l"(a), "l"(b));
}

// ---- pack kernel: gather 12 weight buffers into pair-major staging ----
__global__ void pack_weights_kernel(
    const float* __restrict__ Wq, const float* __restrict__ bq,
    const float* __restrict__ Wk, const float* __restrict__ bk,
    const float* __restrict__ Wv, const float* __restrict__ bv,
    const float* __restrict__ Wo, const float* __restrict__ bo,
    const float* __restrict__ W1, const float* __restrict__ b1,
    const float* __restrict__ W2, const float* __restrict__ b2)
{
    const int t = threadIdx.x;
    for (int i = t; i < 72; i += 256) {
        int e = i / 6, p = i % 6;
        gStage.pWq[i] = pack2(Wq[(2*p) * D + e], Wq[(2*p+1) * D + e]);
        gStage.pWk[i] = pack2(Wk[(2*p) * D + e], Wk[(2*p+1) * D + e]);
        gStage.pWv[i] = pack2(Wv[(2*p) * D + e], Wv[(2*p+1) * D + e]);
        gStage.pWo[i] = pack2(Wo[(2*p) * D + e], Wo[(2*p+1) * D + e]);
    }
    for (int i = t; i < 144; i += 256) {
        int e = i / 12, p = i % 12;
        gStage.pW1[i] = pack2(W1[(2*p) * D + e], W1[(2*p+1) * D + e]);
    }
    for (int i = t; i < 144; i += 256) {
        int f = i / 6, p = i % 6;
        gStage.pW2[i] = pack2(W2[(2*p) * F + f], W2[(2*p+1) * F + f]);
    }
    if (t < 6) {
        gStage.pbq[t] = pack2(bq[2*t], bq[2*t+1]);
        gStage.pbk[t] = pack2(bk[2*t], bk[2*t+1]);
        gStage.pbv[t] = pack2(bv[2*t], bv[2*t+1]);
        gStage.pbo[t] = pack2(bo[2*t], bo[2*t+1]);
        gStage.pb2[t] = pack2(b2[2*t], b2[2*t+1]);
    }
    if (t < 12) gStage.pb1[t] = pack2(b1[2*t], b1[2*t+1]);
}

__global__ __launch_bounds__(THREADS, 3)
void tiny_transformer_kernel(
    const int*   __restrict__ x,
    const float* __restrict__ embed,
    const float* __restrict__ pos,
    const float* __restrict__ blm,
    float* __restrict__ out)
{
    // ---- shared: only lane-divergent data ----
    __shared__ __align__(16) float sEmb[V * D];    // natural [v][d] for gather
    __shared__ __align__(16) float sEmbT[D * V];   // transposed [d][v] for logits
    __shared__ __align__(16) float sPos[N * D];
    __shared__ __align__(16) float sBlm[V];
    __shared__ __align__(16) float sXf[WARPS][IPW * N * D];

    const int tid = threadIdx.x;

    for (int i = tid; i < V * D; i += THREADS) sEmb[i] = embed[i];
    for (int i = tid; i < D * V; i += THREADS) {
        int d = i >> 7, v = i & 127;
        sEmbT[i] = embed[v * D + d];
    }
    for (int i = tid; i < N * D; i += THREADS) sPos[i] = pos[i];
    for (int i = tid; i < V; i += THREADS) sBlm[i] = blm[i];
    __syncthreads();

    const int w    = tid >> 5;
    const int lane = tid & 31;
    const int n    = lane & 7;
    const int item_base = blockIdx.x * ITEMS_PER_BLOCK + w * IPW;

    // ---- phase 1: X = embed[x] + pos ----
    const int tok = __ldg(&x[item_base * N + lane]);
    float X[D];
    #pragma unroll
    for (int c = 0; c < 3; c++) {
        float4 e = F4C(&sEmb[tok * D + 4 * c]);
        float4 p = F4C(&sPos[n * D + 4 * c]);
        X[4*c+0] = e.x + p.x; X[4*c+1] = e.y + p.y;
        X[4*c+2] = e.z + p.z; X[4*c+3] = e.w + p.w;
    }

    // ---- phase 2: Q,K,V (packed FFMA2 against constant port) ----
    float Qr[D], Kr[D], Vr[D];
    {
        ull q2[6], k2[6], v2[6];
        #pragma unroll
        for (int p = 0; p < 6; p++) {
            q2[p] = cw.pbq[p]; k2[p] = cw.pbk[p]; v2[p] = cw.pbv[p];
        }
        #pragma unroll
        for (int e = 0; e < D; e++) {
            const ull xp = pack2(X[e], X[e]);
            #pragma unroll
            for (int p = 0; p < 6; p++) {
                ffma2(q2[p], xp, cw.pWq[e * 6 + p]);
                ffma2(k2[p], xp, cw.pWk[e * 6 + p]);
                ffma2(v2[p], xp, cw.pWv[e * 6 + p]);
            }
        }
        #pragma unroll
        for (int p = 0; p < 6; p++) {
            unpack2(q2[p], Qr[2*p], Qr[2*p+1]);
            unpack2(k2[p], Kr[2*p], Kr[2*p+1]);
            unpack2(v2[p], Vr[2*p], Vr[2*p+1]);
        }
    }

    // ---- phase 3: scores via width-8 shuffles ----
    float S[N];
    {
        const float inv_scale = 0.28867513459481287f;  // 1/sqrt(12)
        #pragma unroll
        for (int m = 0; m < N; m++) {
            float acc = 0.f;
            #pragma unroll
            for (int e = 0; e < D; e++)
                acc += Qr[e] * __shfl_sync(0xffffffffu, Kr[e], m, 8);
            S[m] = (m <= n) ? acc * inv_scale : -1e30f;
        }
    }

    // ---- phase 4: softmax ----
    {
        float mx = S[0];
        #pragma unroll
        for (int m = 1; m < N; m++) mx = fmaxf(mx, S[m]);
        float sum = 0.f;
        #pragma unroll
        for (int m = 0; m < N; m++) { S[m] = __expf(S[m] - mx); sum += S[m]; }
        const float inv = 1.f / sum;
        #pragma unroll
        for (int m = 0; m < N; m++) S[m] *= inv;
    }

    // ---- phase 5: A = softmax @ V via shuffles ----
    float A[D];
    #pragma unroll
    for (int e = 0; e < D; e++) A[e] = 0.f;
    #pragma unroll
    for (int m = 0; m < N; m++) {
        const float s = S[m];
        #pragma unroll
        for (int e = 0; e < D; e++)
            A[e] += s * __shfl_sync(0xffffffffu, Vr[e], m, 8);
    }

    // ---- phase 6: X += A @ Wo^T + bo (packed) ----
    {
        ull o2[6];
        #pragma unroll
        for (int p = 0; p < 6; p++) o2[p] = cw.pbo[p];
        #pragma unroll
        for (int e = 0; e < D; e++) {
            const ull ap = pack2(A[e], A[e]);
            #pragma unroll
            for (int p = 0; p < 6; p++)
                ffma2(o2[p], ap, cw.pWo[e * 6 + p]);
        }
        #pragma unroll
        for (int p = 0; p < 6; p++) {
            float u, v; unpack2(o2[p], u, v);
            X[2*p] += u; X[2*p+1] += v;
        }
    }

    // ---- phase 7: H = relu(X @ W1^T + b1) (packed) ----
    float H[F];
    {
        ull h2[12];
        #pragma unroll
        for (int p = 0; p < 12; p++) h2[p] = cw.pb1[p];
        #pragma unroll
        for (int e = 0; e < D; e++) {
            const ull xp = pack2(X[e], X[e]);
            #pragma unroll
            for (int p = 0; p < 12; p++)
                ffma2(h2[p], xp, cw.pW1[e * 12 + p]);
        }
        #pragma unroll
        for (int p = 0; p < 12; p++) {
            float u, v; unpack2(h2[p], u, v);
            H[2*p]   = fmaxf(u, 0.f);
            H[2*p+1] = fmaxf(v, 0.f);
        }
    }

    // ---- phase 8: X += H @ W2^T + b2 (packed) ----
    {
        ull x2[6];
        #pragma unroll
        for (int p = 0; p < 6; p++) x2[p] = cw.pb2[p];
        #pragma unroll
        for (int f = 0; f < F; f++) {
            const ull hp = pack2(H[f], H[f]);
            #pragma unroll
            for (int p = 0; p < 6; p++)
                ffma2(x2[p], hp, cw.pW2[f * 6 + p]);
        }
        #pragma unroll
        for (int p = 0; p < 6; p++) {
            float u, v; unpack2(x2[p], u, v);
            X[2*p] += u; X[2*p+1] += v;
        }
    }

    // ---- hand off final X ----
    {
        float* dst = &sXf[w][lane * D];
        F4(dst)     = make_float4(X[0], X[1], X[2],  X[3]);
        F4(dst + 4) = make_float4(X[4], X[5], X[6],  X[7]);
        F4(dst + 8) = make_float4(X[8], X[9], X[10], X[11]);
    }
    __syncwarp();

    // ---- phase 9: logits = Xf @ embed^T + b_lm (warp-wide, FFMA2) ----
    {
        const int v0 = lane * 4;
        ull e01[D], e23[D];
        #pragma unroll
        for (int d = 0; d < D; d++) {
            float4 e = F4C(&sEmbT[d * V + v0]);
            e01[d] = pack2(e.x, e.y);
            e23[d] = pack2(e.z, e.w);
        }
        const float4 bl = F4C(&sBlm[v0]);
        const ull bl01 = pack2(bl.x, bl.y);
        const ull bl23 = pack2(bl.z, bl.w);

        float* obase = out + (size_t)item_base * (N * V) + v0;
        const float* xf = sXf[w];

        for (int r = 0; r < IPW * N; r++) {
            float4 xa = F4C(&xf[r * D]);
            float4 xb = F4C(&xf[r * D + 4]);
            float4 xc = F4C(&xf[r * D + 8]);
            const float xr[D] = {xa.x, xa.y, xa.z, xa.w,
                                 xb.x, xb.y, xb.z, xb.w,
                                 xc.x, xc.y, xc.z, xc.w};
            ull a01 = bl01, a23 = bl23;
            #pragma unroll
            for (int d = 0; d < D; d++) {
                const ull xv2 = pack2(xr[d], xr[d]);
                ffma2(a01, xv2, e01[d]);
                ffma2(a23, xv2, e23[d]);
            }
            float4 acc;
            unpack2(a01, acc.x, acc.y);
            unpack2(a23, acc.z, acc.w);
            F4(&obase[(size_t)r * V]) = acc;
        }
    }
}

}  // namespace

extern "C" void kernel_launch(void* const* d_in, const int* in_sizes, int n_in,
                              void* d_out, int out_size)
{
    const int*   x     = (const int*)  d_in[0];
    const float* embed = (const float*)d_in[1];
    const float* pos   = (const float*)d_in[2];
    const float* blm   = (const float*)d_in[15];
    float* out = (float*)d_out;

    // 1) gather + pair-pack all weights into staging (one kernel node)
    pack_weights_kernel<<<1, 256>>>(
        (const float*)d_in[3],  (const float*)d_in[4],
        (const float*)d_in[5],  (const float*)d_in[6],
        (const float*)d_in[7],  (const float*)d_in[8],
        (const float*)d_in[9],  (const float*)d_in[10],
        (const float*)d_in[11], (const float*)d_in[12],
        (const float*)d_in[13], (const float*)d_in[14]);

    // 2) one D2D copy staging -> constant bank (one memcpy node)
    void *dstC, *srcG;
    cudaGetSymbolAddress(&dstC, cw);
    cudaGetSymbolAddress(&srcG, gStage);
    cudaMemcpyAsync(dstC, srcG, sizeof(ConstW), cudaMemcpyDeviceToDevice);

    // 3) main kernel
    const int batch  = in_sizes[0] / N;              // 32768
    const int blocks = batch / ITEMS_PER_BLOCK;      // 1024

    tiny_transformer_kernel<<<blocks, THREADS>>>(x, embed, pos, blm, out);
}